// round 15
// baseline (speedup 1.0000x reference)
#include <cuda_runtime.h>
#include <cuda_bf16.h>

// CNODExtmod R15: R14 + direct-write U operand (race-free):
//  - ep1b holds new cn0 in regs across the barrier, writes U cols 32-63 at
//    start of phase 2 (no U readers in phase 2).
//  - ep3 writes U cols 0-31 + C10/C132 directly (phase 3).
//  - U-build phase and its barrier removed (3 barriers/substep).
//  - obs step does a parallel 128-thread U(0-31) rebuild once per t.

typedef unsigned int u32;

#define TT    64
#define NSUB  4
#define DTC   0.01f
#define NCTA  128
#define NTH   256

#define O_Y2 262144
#define O_T  524288
#define O_H  524352

// ---- SMEM byte offsets (dynamic) ----
#define SM_UH    0         // U operand  [32 x 64]  bf16 hi, rs=128B
#define SM_UL    4096
#define SM_X1H   8192      // X1 operand [32 x 128] bf16 hi, rs=256B
#define SM_X1L   16384
#define SM_X2H   24576
#define SM_X2L   32768
#define SM_W1AH  40960     // W1A [160 x 64]
#define SM_W1AL  61440
#define SM_W2H   81920     // W2 [128 x 128]
#define SM_W2L   114688
#define SM_W3H   147456    // W3ext [40 x 128]
#define SM_W3L   157696
#define SM_CN0   167936    // 32*32 f32
#define SM_CN1   172032    // 32*36 f32 (stride 36)
#define SM_B1    176640
#define SM_B2    177152
#define SM_B3    177664
#define SM_W1C32 177920
#define SM_BV    178432
#define SM_C10   178560
#define SM_C132  178688
#define SM_TOTAL 178816

// ---------------- helpers ----------------
__device__ __forceinline__ u32 s2u(const void* p) {
    u32 a;
    asm("{ .reg .u64 t; cvta.to.shared.u64 t, %1; cvt.u32.u64 %0, t; }"
        : "=r"(a) : "l"(p));
    return a;
}
__device__ __forceinline__ int swoff(int r, int k, int rs) {
    return r * rs + ((((k >> 3) ^ (r & 7)) << 4) | ((k & 7) << 1));
}
__device__ __forceinline__ void ldsm4(u32 a, u32& r0, u32& r1, u32& r2, u32& r3) {
    asm volatile("ldmatrix.sync.aligned.m8n8.x4.shared.b16 {%0,%1,%2,%3},[%4];"
                 : "=r"(r0), "=r"(r1), "=r"(r2), "=r"(r3) : "r"(a));
}
__device__ __forceinline__ void ldsm2(u32 a, u32& r0, u32& r1) {
    asm volatile("ldmatrix.sync.aligned.m8n8.x2.shared.b16 {%0,%1},[%2];"
                 : "=r"(r0), "=r"(r1) : "r"(a));
}
__device__ __forceinline__ void ldA(u32 base, int rs, int mt, int ks, int lane, u32* a) {
    const int quad = lane >> 3, i = lane & 7;
    const int row = mt * 16 + ((quad & 1) << 3) + i;
    const int k   = ks * 16 + ((quad >> 1) << 3);
    ldsm4(base + swoff(row, k, rs), a[0], a[1], a[2], a[3]);
}
__device__ __forceinline__ void ldB(u32 base, int rs, int n0, int ks, int lane, u32* b) {
    const int l = lane & 15;
    const int row = n0 + (l & 7);
    const int k   = ks * 16 + ((l >> 3) << 3);
    ldsm2(base + swoff(row, k, rs), b[0], b[1]);
}
__device__ __forceinline__ void mma16816(float* d, const u32* a, const u32* b) {
    asm volatile(
        "mma.sync.aligned.m16n8k16.row.col.f32.bf16.bf16.f32 "
        "{%0,%1,%2,%3}, {%4,%5,%6,%7}, {%8,%9}, {%0,%1,%2,%3};"
        : "+f"(d[0]), "+f"(d[1]), "+f"(d[2]), "+f"(d[3])
        : "r"(a[0]), "r"(a[1]), "r"(a[2]), "r"(a[3]), "r"(b[0]), "r"(b[1]));
}
__device__ __forceinline__ void mma3(float* d, const u32* ah, const u32* al,
                                     const u32* bh, const u32* bl) {
    mma16816(d, ah, bh);
    mma16816(d, al, bh);
    mma16816(d, ah, bl);
}
__device__ __forceinline__ void hlpair(float va, float vb, u32& ho, u32& lo) {
    __nv_bfloat162 h = __floats2bfloat162_rn(va, vb);
    float ra = va - __low2float(h);
    float rb = vb - __high2float(h);
    __nv_bfloat162 l = __floats2bfloat162_rn(ra, rb);
    ho = *reinterpret_cast<u32*>(&h);
    lo = *reinterpret_cast<u32*>(&l);
}
__device__ __forceinline__ void st_chunk_hl(char* bh, char* bl, int off, const float* v) {
    u32 h[4], l[4];
    #pragma unroll
    for (int p = 0; p < 4; p++) hlpair(v[2 * p], v[2 * p + 1], h[p], l[p]);
    *(uint4*)(bh + off) = make_uint4(h[0], h[1], h[2], h[3]);
    *(uint4*)(bl + off) = make_uint4(l[0], l[1], l[2], l[3]);
}

__global__ void __launch_bounds__(NTH, 1)
cnode_mma_kernel(const float* __restrict__ times, const float* __restrict__ Y,
                 const float* __restrict__ mask,  const float* __restrict__ A,
                 const float* __restrict__ Bvec,
                 const float* __restrict__ W1, const float* __restrict__ b1,
                 const float* __restrict__ W2, const float* __restrict__ b2,
                 const float* __restrict__ W3, const float* __restrict__ b3,
                 float* __restrict__ out)
{
    extern __shared__ __align__(128) char sm[];
    const u32 sb = s2u(sm);
    const int tid  = threadIdx.x;
    const int w    = tid >> 5;      // 0..7
    const int lane = tid & 31;
    const int b0   = blockIdx.x * 32;

    float* CN0S = (float*)(sm + SM_CN0);
    float* CN1S = (float*)(sm + SM_CN1);
    float* B1S  = (float*)(sm + SM_B1);
    float* B2S  = (float*)(sm + SM_B2);
    float* B3S  = (float*)(sm + SM_B3);
    float* W1C  = (float*)(sm + SM_W1C32);
    float* BV   = (float*)(sm + SM_BV);
    float* C10  = (float*)(sm + SM_C10);
    float* C132 = (float*)(sm + SM_C132);

    // ---------------- one-time weight conversion ----------------
    {
        float v[8];
        for (int r = tid; r < 160; r += NTH) {
            #pragma unroll
            for (int c8 = 0; c8 < 8; c8++) {
                #pragma unroll
                for (int i = 0; i < 8; i++) {
                    const int k = c8 * 8 + i;
                    float x;
                    if (r < 128) x = (k < 32) ? W1[r * 33 + k] : 0.0f;
                    else         x = (k >= 32) ? A[(r - 128) * 32 + (k - 32)] : 0.0f;
                    v[i] = x;
                }
                const int off = swoff(r, c8 * 8, 128);
                st_chunk_hl(sm + SM_W1AH, sm + SM_W1AL, off, v);
            }
        }
        {
            const int r = tid >> 1, hh = tid & 1;
            #pragma unroll
            for (int c8 = hh * 8; c8 < hh * 8 + 8; c8++) {
                #pragma unroll
                for (int i = 0; i < 8; i++) v[i] = W2[r * 128 + c8 * 8 + i];
                const int off = swoff(r, c8 * 8, 256);
                st_chunk_hl(sm + SM_W2H, sm + SM_W2L, off, v);
            }
        }
        if (tid < 80) {
            const int r = tid >> 1, hh = tid & 1;
            #pragma unroll
            for (int c8 = hh * 8; c8 < hh * 8 + 8; c8++) {
                #pragma unroll
                for (int i = 0; i < 8; i++)
                    v[i] = (r < 33) ? W3[r * 128 + c8 * 8 + i] : 0.0f;
                const int off = swoff(r, c8 * 8, 256);
                st_chunk_hl(sm + SM_W3H, sm + SM_W3L, off, v);
            }
        }
        if (tid < 128) {
            B1S[tid] = b1[tid];
            B2S[tid] = b2[tid];
            W1C[tid] = W1[tid * 33 + 32];
        }
        if (tid < 40) B3S[tid] = (tid < 33) ? b3[tid] : 0.0f;
        if (tid < 32) { BV[tid] = Bvec[tid]; C10[tid] = 0.0f; C132[tid] = 0.0f; }
        for (int i = tid; i < 32 * 32; i += NTH) CN0S[i] = 0.0f;
        for (int i = tid; i < 32 * 36; i += NTH) CN1S[i] = 0.0f;
        // U starts as zeros (state is zero)
        for (int i = tid; i < 1024; i += NTH) {
            ((u32*)(sm + SM_UH))[i] = 0u;
            ((u32*)(sm + SM_UL))[i] = 0u;
        }
    }
    if (blockIdx.x == 0 && tid < TT) out[O_T + tid] = times[tid];

    float y_t = 0.0f, m_t = 0.0f;
    if (tid < 32) {
        y_t = Y[(b0 + tid) * TT];
        m_t = mask[(b0 + tid) * TT];
    }
    __syncthreads();

    const u32 bUH  = sb + SM_UH,  bUL  = sb + SM_UL;
    const u32 bX1H = sb + SM_X1H, bX1L = sb + SM_X1L;
    const u32 bX2H = sb + SM_X2H, bX2L = sb + SM_X2L;
    const u32 bW1H = sb + SM_W1AH, bW1L = sb + SM_W1AL;
    const u32 bW2H = sb + SM_W2H,  bW2L = sb + SM_W2L;
    const u32 bW3H = sb + SM_W3H,  bW3L = sb + SM_W3L;

    // ---- hoist ALL loop-invariant B fragments into registers ----
    u32 B1h[2][2][2], B1l[2][2][2];
    #pragma unroll
    for (int ks = 0; ks < 2; ks++)
        #pragma unroll
        for (int it = 0; it < 2; it++) {
            const int n0 = (w + it * 8) * 8;
            ldB(bW1H, 128, n0, ks, lane, B1h[ks][it]);
            ldB(bW1L, 128, n0, ks, lane, B1l[ks][it]);
        }
    u32 BAh[2][2], BAl[2][2];
    if (w < 4) {
        #pragma unroll
        for (int k2 = 0; k2 < 2; k2++) {
            ldB(bW1H, 128, 128 + w * 8, k2 + 2, lane, BAh[k2]);
            ldB(bW1L, 128, 128 + w * 8, k2 + 2, lane, BAl[k2]);
        }
    }
    u32 B2rh[8][2][2], B2rl[8][2][2];
    #pragma unroll
    for (int ks = 0; ks < 8; ks++)
        #pragma unroll
        for (int it = 0; it < 2; it++) {
            const int n0 = (w + it * 8) * 8;
            ldB(bW2H, 256, n0, ks, lane, B2rh[ks][it]);
            ldB(bW2L, 256, n0, ks, lane, B2rl[ks][it]);
        }
    u32 B3h[8][2], B3l[8][2];
    if (w < 5) {
        #pragma unroll
        for (int ks = 0; ks < 8; ks++) {
            ldB(bW3H, 256, w * 8, ks, lane, B3h[ks]);
            ldB(bW3L, 256, w * 8, ks, lane, B3l[ks]);
        }
    }

    for (int t = 0; t < TT; t++) {
        for (int sub = 0; sub < NSUB; sub++) {
            // ========== phase 1: GEMM1 [X1 | dcn0] = U @ W1A^T ==========
            float aX[2][2][4] = {};
            float aA[2][4] = {};
            {
                u32 Ah[2][4], Al[2][4];
                #pragma unroll
                for (int ks = 0; ks < 2; ks++) {
                    #pragma unroll
                    for (int mt = 0; mt < 2; mt++) {
                        ldA(bUH, 128, mt, ks, lane, Ah[mt]);
                        ldA(bUL, 128, mt, ks, lane, Al[mt]);
                    }
                    #pragma unroll
                    for (int it = 0; it < 2; it++)
                        #pragma unroll
                        for (int mt = 0; mt < 2; mt++)
                            mma3(aX[it][mt], Ah[mt], Al[mt], B1h[ks][it], B1l[ks][it]);
                }
                if (w < 4) {
                    #pragma unroll
                    for (int k2 = 0; k2 < 2; k2++) {
                        #pragma unroll
                        for (int mt = 0; mt < 2; mt++) {
                            ldA(bUH, 128, mt, k2 + 2, lane, Ah[mt]);
                            ldA(bUL, 128, mt, k2 + 2, lane, Al[mt]);
                        }
                        #pragma unroll
                        for (int mt = 0; mt < 2; mt++)
                            mma3(aA[mt], Ah[mt], Al[mt], BAh[k2], BAl[k2]);
                    }
                }
            }
            // ep1: X1 = relu(d + W1[:,32]*cn1[32] + b1) -> hi/lo SMEM
            #pragma unroll
            for (int it = 0; it < 2; it++) {
                const int c0 = (w + it * 8) * 8 + 2 * (lane & 3);
                const float w1a = W1C[c0], w1b = W1C[c0 + 1];
                const float bb1 = B1S[c0], bb2 = B1S[c0 + 1];
                #pragma unroll
                for (int mt = 0; mt < 2; mt++) {
                    #pragma unroll
                    for (int hh = 0; hh < 2; hh++) {
                        const int r = mt * 16 + (lane >> 2) + hh * 8;
                        const float cx = C132[r];
                        float va = fmaxf(aX[it][mt][hh*2+0] + w1a * cx + bb1, 0.0f);
                        float vb = fmaxf(aX[it][mt][hh*2+1] + w1b * cx + bb2, 0.0f);
                        u32 ho, lo; hlpair(va, vb, ho, lo);
                        const int off = swoff(r, c0, 256);
                        *(u32*)(sm + SM_X1H + off) = ho;
                        *(u32*)(sm + SM_X1L + off) = lo;
                    }
                }
            }
            // ep1b: cn0 += dt*(dcn0 + Bvec*cn1[0]); keep new cn0 in regs
            float nc0[2][2][2];                // [mt][hh][pair]
            if (w < 4) {
                const int c0 = w * 8 + 2 * (lane & 3);
                const float bva = BV[c0], bvb = BV[c0 + 1];
                #pragma unroll
                for (int mt = 0; mt < 2; mt++) {
                    #pragma unroll
                    for (int hh = 0; hh < 2; hh++) {
                        const int r = mt * 16 + (lane >> 2) + hh * 8;
                        const float c1v = C10[r];
                        float v0 = CN0S[r * 32 + c0]     + DTC * (aA[mt][hh*2+0] + bva * c1v);
                        float v1 = CN0S[r * 32 + c0 + 1] + DTC * (aA[mt][hh*2+1] + bvb * c1v);
                        CN0S[r * 32 + c0]     = v0;
                        CN0S[r * 32 + c0 + 1] = v1;
                        nc0[mt][hh][0] = v0;
                        nc0[mt][hh][1] = v1;
                    }
                }
            }
            __syncthreads();

            // ========== phase 2: U(cols 32-63) write, then GEMM2 ==========
            if (w < 4) {
                const int c0 = w * 8 + 2 * (lane & 3);
                #pragma unroll
                for (int mt = 0; mt < 2; mt++) {
                    #pragma unroll
                    for (int hh = 0; hh < 2; hh++) {
                        const int r = mt * 16 + (lane >> 2) + hh * 8;
                        u32 ho, lo; hlpair(nc0[mt][hh][0], nc0[mt][hh][1], ho, lo);
                        const int off = swoff(r, 32 + c0, 128);
                        *(u32*)(sm + SM_UH + off) = ho;
                        *(u32*)(sm + SM_UL + off) = lo;
                    }
                }
            }
            float a2[2][2][4] = {};
            {
                u32 Ah[2][4], Al[2][4];
                #pragma unroll
                for (int ks = 0; ks < 8; ks++) {
                    #pragma unroll
                    for (int mt = 0; mt < 2; mt++) {
                        ldA(bX1H, 256, mt, ks, lane, Ah[mt]);
                        ldA(bX1L, 256, mt, ks, lane, Al[mt]);
                    }
                    #pragma unroll
                    for (int it = 0; it < 2; it++)
                        #pragma unroll
                        for (int mt = 0; mt < 2; mt++)
                            mma3(a2[it][mt], Ah[mt], Al[mt],
                                 B2rh[ks][it], B2rl[ks][it]);
                }
            }
            #pragma unroll
            for (int it = 0; it < 2; it++) {
                const int c0 = (w + it * 8) * 8 + 2 * (lane & 3);
                const float bb1 = B2S[c0], bb2 = B2S[c0 + 1];
                #pragma unroll
                for (int mt = 0; mt < 2; mt++) {
                    #pragma unroll
                    for (int hh = 0; hh < 2; hh++) {
                        const int r = mt * 16 + (lane >> 2) + hh * 8;
                        float va = fmaxf(a2[it][mt][hh*2+0] + bb1, 0.0f);
                        float vb = fmaxf(a2[it][mt][hh*2+1] + bb2, 0.0f);
                        u32 ho, lo; hlpair(va, vb, ho, lo);
                        const int off = swoff(r, c0, 256);
                        *(u32*)(sm + SM_X2H + off) = ho;
                        *(u32*)(sm + SM_X2L + off) = lo;
                    }
                }
            }
            __syncthreads();

            // ========== phase 3: GEMM3 + ep3 (cn1 + U cols 0-31) ==========
            if (w < 5) {
                float a3[2][4] = {};
                u32 Ah[2][4], Al[2][4];
                #pragma unroll
                for (int ks = 0; ks < 8; ks++) {
                    #pragma unroll
                    for (int mt = 0; mt < 2; mt++) {
                        ldA(bX2H, 256, mt, ks, lane, Ah[mt]);
                        ldA(bX2L, 256, mt, ks, lane, Al[mt]);
                    }
                    #pragma unroll
                    for (int mt = 0; mt < 2; mt++)
                        mma3(a3[mt], Ah[mt], Al[mt], B3h[ks], B3l[ks]);
                }
                const int c0 = w * 8 + 2 * (lane & 3);
                #pragma unroll
                for (int mt = 0; mt < 2; mt++) {
                    #pragma unroll
                    for (int hh = 0; hh < 2; hh++) {
                        const int r = mt * 16 + (lane >> 2) + hh * 8;
                        float v0 = 0.0f, v1 = 0.0f;
                        if (c0 <= 32) {
                            v0 = CN1S[r * 36 + c0] + DTC * (a3[mt][hh*2+0] + B3S[c0]);
                            CN1S[r * 36 + c0] = v0;
                        }
                        if (c0 + 1 <= 32) {
                            v1 = CN1S[r * 36 + c0 + 1] + DTC * (a3[mt][hh*2+1] + B3S[c0 + 1]);
                            CN1S[r * 36 + c0 + 1] = v1;
                        }
                        if (c0 < 32) {   // cn1[0..31] -> U cols 0..31
                            u32 ho, lo; hlpair(v0, v1, ho, lo);
                            const int off = swoff(r, c0, 128);
                            *(u32*)(sm + SM_UH + off) = ho;
                            *(u32*)(sm + SM_UL + off) = lo;
                        }
                        if (c0 == 0)  C10[r]  = v0;
                        if (c0 == 32) C132[r] = v0;
                    }
                }
            }
            __syncthreads();
        }

        // ---------- observation step ----------
        if (tid < 32) {
            const int r = tid;
            const float yp = CN1S[r * 36];
            out[(b0 + r) * TT + t]        = yp;
            out[O_Y2 + (b0 + r) * TT + t] = yp;
            if (m_t != 0.0f) {
                CN1S[r * 36] = y_t;
                #pragma unroll
                for (int j = 1; j < 33; j++)
                    CN1S[r * 36 + j] = CN0S[r * 32 + j - 1];
            }
            if (t + 1 < TT) {
                y_t = Y[(b0 + r) * TT + t + 1];
                m_t = mask[(b0 + r) * TT + t + 1];
            }
        }
        __syncthreads();
        // parallel rebuild of U cols 0-31 from (possibly masked) CN1S,
        // plus C10/C132 refresh. U cols 32-63 (cn0) unchanged by obs.
        if (tid < 128) {
            const int r = tid >> 2, c8 = tid & 3;
            float v[8];
            const float* s = CN1S + r * 36 + c8 * 8;
            float4 f0 = *(const float4*)(s);
            float4 f1 = *(const float4*)(s + 4);
            v[0]=f0.x; v[1]=f0.y; v[2]=f0.z; v[3]=f0.w;
            v[4]=f1.x; v[5]=f1.y; v[6]=f1.z; v[7]=f1.w;
            st_chunk_hl(sm + SM_UH, sm + SM_UL, swoff(r, c8 * 8, 128), v);
            if (c8 == 0) {
                C10[r]  = CN1S[r * 36];
                C132[r] = CN1S[r * 36 + 32];
            }
        }
        __syncthreads();
    }

    // final hidden state cn0
    if (tid < 32) {
        const int r = tid;
        #pragma unroll
        for (int p = 0; p < 8; p++) {
            float4 f = *(const float4*)(CN0S + r * 32 + 4 * p);
            *(float4*)(out + O_H + (b0 + r) * 32 + 4 * p) = f;
        }
    }
}

extern "C" void kernel_launch(void* const* d_in, const int* in_sizes, int n_in,
                              void* d_out, int out_size)
{
    const float* times = (const float*)d_in[0];
    const float* Y     = (const float*)d_in[1];
    const float* mask  = (const float*)d_in[2];
    const float* A     = (const float*)d_in[3];
    const float* Bvec  = (const float*)d_in[4];
    const float* W1    = (const float*)d_in[5];
    const float* b1    = (const float*)d_in[6];
    const float* W2    = (const float*)d_in[7];
    const float* b2    = (const float*)d_in[8];
    const float* W3    = (const float*)d_in[9];
    const float* b3    = (const float*)d_in[10];
    float* out = (float*)d_out;

    cudaFuncSetAttribute(cnode_mma_kernel,
                         cudaFuncAttributeMaxDynamicSharedMemorySize, SM_TOTAL);
    cnode_mma_kernel<<<NCTA, NTH, SM_TOTAL>>>(times, Y, mask, A, Bvec,
                                              W1, b1, W2, b2, W3, b3, out);
}

// round 16
// speedup vs baseline: 1.1232x; 1.1232x over previous
#include <cuda_runtime.h>
#include <cuda_bf16.h>

// CNODExtmod R16: R14 + A-block (dcn0) moved from phase-1 warps 0-3 to
// phase-3 warps 5-7 (idle under GEMM3). Phase 1 uniform across 8 warps.
// U cols 32-63 maintained by phase-3 writers; U-build covers cols 0-31 only.

typedef unsigned int u32;

#define TT    64
#define NSUB  4
#define DTC   0.01f
#define NCTA  128
#define NTH   256

#define O_Y2 262144
#define O_T  524288
#define O_H  524352

// ---- SMEM byte offsets (dynamic) ----
#define SM_UH    0         // U operand  [32 x 64]  bf16 hi, rs=128B
#define SM_UL    4096
#define SM_X1H   8192      // X1 operand [32 x 128] bf16 hi, rs=256B
#define SM_X1L   16384
#define SM_X2H   24576
#define SM_X2L   32768
#define SM_W1AH  40960     // W1A [160 x 64]
#define SM_W1AL  61440
#define SM_W2H   81920     // W2 [128 x 128]
#define SM_W2L   114688
#define SM_W3H   147456    // W3ext [40 x 128]
#define SM_W3L   157696
#define SM_CN0   167936    // 32*32 f32
#define SM_CN1   172032    // 32*36 f32 (stride 36)
#define SM_B1    176640
#define SM_B2    177152
#define SM_B3    177664
#define SM_W1C32 177920
#define SM_BV    178432
#define SM_C10   178560
#define SM_C132  178688
#define SM_TOTAL 178816

// ---------------- helpers ----------------
__device__ __forceinline__ u32 s2u(const void* p) {
    u32 a;
    asm("{ .reg .u64 t; cvta.to.shared.u64 t, %1; cvt.u32.u64 %0, t; }"
        : "=r"(a) : "l"(p));
    return a;
}
__device__ __forceinline__ int swoff(int r, int k, int rs) {
    return r * rs + ((((k >> 3) ^ (r & 7)) << 4) | ((k & 7) << 1));
}
__device__ __forceinline__ void ldsm4(u32 a, u32& r0, u32& r1, u32& r2, u32& r3) {
    asm volatile("ldmatrix.sync.aligned.m8n8.x4.shared.b16 {%0,%1,%2,%3},[%4];"
                 : "=r"(r0), "=r"(r1), "=r"(r2), "=r"(r3) : "r"(a));
}
__device__ __forceinline__ void ldsm2(u32 a, u32& r0, u32& r1) {
    asm volatile("ldmatrix.sync.aligned.m8n8.x2.shared.b16 {%0,%1},[%2];"
                 : "=r"(r0), "=r"(r1) : "r"(a));
}
__device__ __forceinline__ void ldA(u32 base, int rs, int mt, int ks, int lane, u32* a) {
    const int quad = lane >> 3, i = lane & 7;
    const int row = mt * 16 + ((quad & 1) << 3) + i;
    const int k   = ks * 16 + ((quad >> 1) << 3);
    ldsm4(base + swoff(row, k, rs), a[0], a[1], a[2], a[3]);
}
__device__ __forceinline__ void ldB(u32 base, int rs, int n0, int ks, int lane, u32* b) {
    const int l = lane & 15;
    const int row = n0 + (l & 7);
    const int k   = ks * 16 + ((l >> 3) << 3);
    ldsm2(base + swoff(row, k, rs), b[0], b[1]);
}
__device__ __forceinline__ void mma16816(float* d, const u32* a, const u32* b) {
    asm volatile(
        "mma.sync.aligned.m16n8k16.row.col.f32.bf16.bf16.f32 "
        "{%0,%1,%2,%3}, {%4,%5,%6,%7}, {%8,%9}, {%0,%1,%2,%3};"
        : "+f"(d[0]), "+f"(d[1]), "+f"(d[2]), "+f"(d[3])
        : "r"(a[0]), "r"(a[1]), "r"(a[2]), "r"(a[3]), "r"(b[0]), "r"(b[1]));
}
__device__ __forceinline__ void mma3(float* d, const u32* ah, const u32* al,
                                     const u32* bh, const u32* bl) {
    mma16816(d, ah, bh);
    mma16816(d, al, bh);
    mma16816(d, ah, bl);
}
__device__ __forceinline__ void hlpair(float va, float vb, u32& ho, u32& lo) {
    __nv_bfloat162 h = __floats2bfloat162_rn(va, vb);
    float ra = va - __low2float(h);
    float rb = vb - __high2float(h);
    __nv_bfloat162 l = __floats2bfloat162_rn(ra, rb);
    ho = *reinterpret_cast<u32*>(&h);
    lo = *reinterpret_cast<u32*>(&l);
}
__device__ __forceinline__ void st_chunk_hl(char* bh, char* bl, int off, const float* v) {
    u32 h[4], l[4];
    #pragma unroll
    for (int p = 0; p < 4; p++) hlpair(v[2 * p], v[2 * p + 1], h[p], l[p]);
    *(uint4*)(bh + off) = make_uint4(h[0], h[1], h[2], h[3]);
    *(uint4*)(bl + off) = make_uint4(l[0], l[1], l[2], l[3]);
}

__global__ void __launch_bounds__(NTH, 1)
cnode_mma_kernel(const float* __restrict__ times, const float* __restrict__ Y,
                 const float* __restrict__ mask,  const float* __restrict__ A,
                 const float* __restrict__ Bvec,
                 const float* __restrict__ W1, const float* __restrict__ b1,
                 const float* __restrict__ W2, const float* __restrict__ b2,
                 const float* __restrict__ W3, const float* __restrict__ b3,
                 float* __restrict__ out)
{
    extern __shared__ __align__(128) char sm[];
    const u32 sb = s2u(sm);
    const int tid  = threadIdx.x;
    const int w    = tid >> 5;      // 0..7
    const int lane = tid & 31;
    const int b0   = blockIdx.x * 32;

    float* CN0S = (float*)(sm + SM_CN0);
    float* CN1S = (float*)(sm + SM_CN1);
    float* B1S  = (float*)(sm + SM_B1);
    float* B2S  = (float*)(sm + SM_B2);
    float* B3S  = (float*)(sm + SM_B3);
    float* W1C  = (float*)(sm + SM_W1C32);
    float* BV   = (float*)(sm + SM_BV);
    float* C10  = (float*)(sm + SM_C10);
    float* C132 = (float*)(sm + SM_C132);

    // ---------------- one-time weight conversion ----------------
    {
        float v[8];
        for (int r = tid; r < 160; r += NTH) {
            #pragma unroll
            for (int c8 = 0; c8 < 8; c8++) {
                #pragma unroll
                for (int i = 0; i < 8; i++) {
                    const int k = c8 * 8 + i;
                    float x;
                    if (r < 128) x = (k < 32) ? W1[r * 33 + k] : 0.0f;
                    else         x = (k >= 32) ? A[(r - 128) * 32 + (k - 32)] : 0.0f;
                    v[i] = x;
                }
                const int off = swoff(r, c8 * 8, 128);
                st_chunk_hl(sm + SM_W1AH, sm + SM_W1AL, off, v);
            }
        }
        {
            const int r = tid >> 1, hh = tid & 1;
            #pragma unroll
            for (int c8 = hh * 8; c8 < hh * 8 + 8; c8++) {
                #pragma unroll
                for (int i = 0; i < 8; i++) v[i] = W2[r * 128 + c8 * 8 + i];
                const int off = swoff(r, c8 * 8, 256);
                st_chunk_hl(sm + SM_W2H, sm + SM_W2L, off, v);
            }
        }
        if (tid < 80) {
            const int r = tid >> 1, hh = tid & 1;
            #pragma unroll
            for (int c8 = hh * 8; c8 < hh * 8 + 8; c8++) {
                #pragma unroll
                for (int i = 0; i < 8; i++)
                    v[i] = (r < 33) ? W3[r * 128 + c8 * 8 + i] : 0.0f;
                const int off = swoff(r, c8 * 8, 256);
                st_chunk_hl(sm + SM_W3H, sm + SM_W3L, off, v);
            }
        }
        if (tid < 128) {
            B1S[tid] = b1[tid];
            B2S[tid] = b2[tid];
            W1C[tid] = W1[tid * 33 + 32];
        }
        if (tid < 40) B3S[tid] = (tid < 33) ? b3[tid] : 0.0f;
        if (tid < 32) { BV[tid] = Bvec[tid]; C10[tid] = 0.0f; C132[tid] = 0.0f; }
        for (int i = tid; i < 32 * 32; i += NTH) CN0S[i] = 0.0f;
        for (int i = tid; i < 32 * 36; i += NTH) CN1S[i] = 0.0f;
        // U starts as zeros (state is zero); cols 32-63 maintained in-loop
        for (int i = tid; i < 1024; i += NTH) {
            ((u32*)(sm + SM_UH))[i] = 0u;
            ((u32*)(sm + SM_UL))[i] = 0u;
        }
    }
    if (blockIdx.x == 0 && tid < TT) out[O_T + tid] = times[tid];

    float y_t = 0.0f, m_t = 0.0f;
    if (tid < 32) {
        y_t = Y[(b0 + tid) * TT];
        m_t = mask[(b0 + tid) * TT];
    }
    __syncthreads();

    const u32 bUH  = sb + SM_UH,  bUL  = sb + SM_UL;
    const u32 bX1H = sb + SM_X1H, bX1L = sb + SM_X1L;
    const u32 bX2H = sb + SM_X2H, bX2L = sb + SM_X2L;
    const u32 bW1H = sb + SM_W1AH, bW1L = sb + SM_W1AL;
    const u32 bW2H = sb + SM_W2H,  bW2L = sb + SM_W2L;
    const u32 bW3H = sb + SM_W3H,  bW3L = sb + SM_W3L;

    // ---- hoist ALL loop-invariant B fragments into registers ----
    u32 B1h[2][2][2], B1l[2][2][2];           // W1A n<128: [ks][it][frag]
    #pragma unroll
    for (int ks = 0; ks < 2; ks++)
        #pragma unroll
        for (int it = 0; it < 2; it++) {
            const int n0 = (w + it * 8) * 8;
            ldB(bW1H, 128, n0, ks, lane, B1h[ks][it]);
            ldB(bW1L, 128, n0, ks, lane, B1l[ks][it]);
        }
    // A-block tiles on warps 5-7: w5 -> {0,1}, w6 -> {2}, w7 -> {3}
    int natile = 0;
    int atl0 = 0, atl1 = 1;
    if (w == 5) { natile = 2; atl0 = 0; atl1 = 1; }
    else if (w == 6) { natile = 1; atl0 = 2; }
    else if (w == 7) { natile = 1; atl0 = 3; }
    u32 BAh[2][2][2], BAl[2][2][2];           // [ti][k2][frag]
    for (int ti = 0; ti < natile; ti++) {
        const int at = (ti == 0) ? atl0 : atl1;
        #pragma unroll
        for (int k2 = 0; k2 < 2; k2++) {
            ldB(bW1H, 128, 128 + at * 8, k2 + 2, lane, BAh[ti][k2]);
            ldB(bW1L, 128, 128 + at * 8, k2 + 2, lane, BAl[ti][k2]);
        }
    }
    u32 B2rh[8][2][2], B2rl[8][2][2];         // W2 all ks: [ks][it][frag]
    #pragma unroll
    for (int ks = 0; ks < 8; ks++)
        #pragma unroll
        for (int it = 0; it < 2; it++) {
            const int n0 = (w + it * 8) * 8;
            ldB(bW2H, 256, n0, ks, lane, B2rh[ks][it]);
            ldB(bW2L, 256, n0, ks, lane, B2rl[ks][it]);
        }
    u32 B3h[8][2], B3l[8][2];                 // W3, warps 0-4, all ks
    if (w < 5) {
        #pragma unroll
        for (int ks = 0; ks < 8; ks++) {
            ldB(bW3H, 256, w * 8, ks, lane, B3h[ks]);
            ldB(bW3L, 256, w * 8, ks, lane, B3l[ks]);
        }
    }

    for (int t = 0; t < TT; t++) {
        for (int sub = 0; sub < NSUB; sub++) {
            // ===== phase 0: U build cols 0-31 (cn1) + C10/C132 refresh =====
            if (tid < 128) {
                const int r = tid >> 2, c8 = tid & 3;
                float v[8];
                const float* s = CN1S + r * 36 + c8 * 8;
                float4 f0 = *(const float4*)(s);
                float4 f1 = *(const float4*)(s + 4);
                v[0]=f0.x; v[1]=f0.y; v[2]=f0.z; v[3]=f0.w;
                v[4]=f1.x; v[5]=f1.y; v[6]=f1.z; v[7]=f1.w;
                st_chunk_hl(sm + SM_UH, sm + SM_UL, swoff(r, c8 * 8, 128), v);
                if (c8 == 0) {
                    C10[r]  = CN1S[r * 36];
                    C132[r] = CN1S[r * 36 + 32];
                }
            }
            __syncthreads();

            // ===== phase 1: GEMM1 X1 = relu(U @ W1^T ...) — uniform 8 warps =====
            float aX[2][2][4] = {};
            {
                u32 Ah[2][4], Al[2][4];
                #pragma unroll
                for (int ks = 0; ks < 2; ks++) {
                    #pragma unroll
                    for (int mt = 0; mt < 2; mt++) {
                        ldA(bUH, 128, mt, ks, lane, Ah[mt]);
                        ldA(bUL, 128, mt, ks, lane, Al[mt]);
                    }
                    #pragma unroll
                    for (int it = 0; it < 2; it++)
                        #pragma unroll
                        for (int mt = 0; mt < 2; mt++)
                            mma3(aX[it][mt], Ah[mt], Al[mt], B1h[ks][it], B1l[ks][it]);
                }
            }
            #pragma unroll
            for (int it = 0; it < 2; it++) {
                const int c0 = (w + it * 8) * 8 + 2 * (lane & 3);
                const float w1a = W1C[c0], w1b = W1C[c0 + 1];
                const float bb1 = B1S[c0], bb2 = B1S[c0 + 1];
                #pragma unroll
                for (int mt = 0; mt < 2; mt++) {
                    #pragma unroll
                    for (int hh = 0; hh < 2; hh++) {
                        const int r = mt * 16 + (lane >> 2) + hh * 8;
                        const float cx = C132[r];
                        float va = fmaxf(aX[it][mt][hh*2+0] + w1a * cx + bb1, 0.0f);
                        float vb = fmaxf(aX[it][mt][hh*2+1] + w1b * cx + bb2, 0.0f);
                        u32 ho, lo; hlpair(va, vb, ho, lo);
                        const int off = swoff(r, c0, 256);
                        *(u32*)(sm + SM_X1H + off) = ho;
                        *(u32*)(sm + SM_X1L + off) = lo;
                    }
                }
            }
            __syncthreads();

            // ===== phase 2: GEMM2 X2 = relu(X1 @ W2^T + b2) (no ldB) =====
            float a2[2][2][4] = {};
            {
                u32 Ah[2][4], Al[2][4];
                #pragma unroll
                for (int ks = 0; ks < 8; ks++) {
                    #pragma unroll
                    for (int mt = 0; mt < 2; mt++) {
                        ldA(bX1H, 256, mt, ks, lane, Ah[mt]);
                        ldA(bX1L, 256, mt, ks, lane, Al[mt]);
                    }
                    #pragma unroll
                    for (int it = 0; it < 2; it++)
                        #pragma unroll
                        for (int mt = 0; mt < 2; mt++)
                            mma3(a2[it][mt], Ah[mt], Al[mt],
                                 B2rh[ks][it], B2rl[ks][it]);
                }
            }
            #pragma unroll
            for (int it = 0; it < 2; it++) {
                const int c0 = (w + it * 8) * 8 + 2 * (lane & 3);
                const float bb1 = B2S[c0], bb2 = B2S[c0 + 1];
                #pragma unroll
                for (int mt = 0; mt < 2; mt++) {
                    #pragma unroll
                    for (int hh = 0; hh < 2; hh++) {
                        const int r = mt * 16 + (lane >> 2) + hh * 8;
                        float va = fmaxf(a2[it][mt][hh*2+0] + bb1, 0.0f);
                        float vb = fmaxf(a2[it][mt][hh*2+1] + bb2, 0.0f);
                        u32 ho, lo; hlpair(va, vb, ho, lo);
                        const int off = swoff(r, c0, 256);
                        *(u32*)(sm + SM_X2H + off) = ho;
                        *(u32*)(sm + SM_X2L + off) = lo;
                    }
                }
            }
            __syncthreads();

            // ===== phase 3: GEMM3 (warps 0-4) || A-block dcn0 (warps 5-7) =====
            if (w < 5) {
                float a3[2][4] = {};
                u32 Ah[2][4], Al[2][4];
                #pragma unroll
                for (int ks = 0; ks < 8; ks++) {
                    #pragma unroll
                    for (int mt = 0; mt < 2; mt++) {
                        ldA(bX2H, 256, mt, ks, lane, Ah[mt]);
                        ldA(bX2L, 256, mt, ks, lane, Al[mt]);
                    }
                    #pragma unroll
                    for (int mt = 0; mt < 2; mt++)
                        mma3(a3[mt], Ah[mt], Al[mt], B3h[ks], B3l[ks]);
                }
                const int c0 = w * 8 + 2 * (lane & 3);
                #pragma unroll
                for (int mt = 0; mt < 2; mt++) {
                    #pragma unroll
                    for (int hh = 0; hh < 2; hh++) {
                        const int r = mt * 16 + (lane >> 2) + hh * 8;
                        if (c0 <= 32)
                            CN1S[r * 36 + c0]     += DTC * (a3[mt][hh*2+0] + B3S[c0]);
                        if (c0 + 1 <= 32)
                            CN1S[r * 36 + c0 + 1] += DTC * (a3[mt][hh*2+1] + B3S[c0 + 1]);
                    }
                }
            } else {
                // warps 5-7: dcn0 = U(cn0) @ A^T + Bvec*cn1[0]; cn0 Euler
                // update; rewrite U cols 32-63 from registers.
                u32 Ah[2][2][4], Al[2][2][4];      // [k2][mt]
                #pragma unroll
                for (int k2 = 0; k2 < 2; k2++)
                    #pragma unroll
                    for (int mt = 0; mt < 2; mt++) {
                        ldA(bUH, 128, mt, k2 + 2, lane, Ah[k2][mt]);
                        ldA(bUL, 128, mt, k2 + 2, lane, Al[k2][mt]);
                    }
                // all 3 warps done READING U cols 32-63 before any write
                asm volatile("bar.sync 1, 96;" ::: "memory");
                float aA[2][2][4] = {};            // [ti][mt]
                for (int ti = 0; ti < natile; ti++)
                    #pragma unroll
                    for (int k2 = 0; k2 < 2; k2++)
                        #pragma unroll
                        for (int mt = 0; mt < 2; mt++)
                            mma3(aA[ti][mt], Ah[k2][mt], Al[k2][mt],
                                 BAh[ti][k2], BAl[ti][k2]);
                for (int ti = 0; ti < natile; ti++) {
                    const int at = (ti == 0) ? atl0 : atl1;
                    const int c0 = at * 8 + 2 * (lane & 3);
                    const float bva = BV[c0], bvb = BV[c0 + 1];
                    #pragma unroll
                    for (int mt = 0; mt < 2; mt++) {
                        #pragma unroll
                        for (int hh = 0; hh < 2; hh++) {
                            const int r = mt * 16 + (lane >> 2) + hh * 8;
                            const float c1v = C10[r];
                            float v0 = CN0S[r * 32 + c0]
                                     + DTC * (aA[ti][mt][hh*2+0] + bva * c1v);
                            float v1 = CN0S[r * 32 + c0 + 1]
                                     + DTC * (aA[ti][mt][hh*2+1] + bvb * c1v);
                            CN0S[r * 32 + c0]     = v0;
                            CN0S[r * 32 + c0 + 1] = v1;
                            u32 ho, lo; hlpair(v0, v1, ho, lo);
                            const int off = swoff(r, 32 + c0, 128);
                            *(u32*)(sm + SM_UH + off) = ho;
                            *(u32*)(sm + SM_UL + off) = lo;
                        }
                    }
                }
            }
            __syncthreads();
        }

        // ---------- observation step ----------
        if (tid < 32) {
            const int r = tid;
            const float yp = CN1S[r * 36];
            out[(b0 + r) * TT + t]        = yp;
            out[O_Y2 + (b0 + r) * TT + t] = yp;
            if (m_t != 0.0f) {
                CN1S[r * 36] = y_t;
                #pragma unroll
                for (int j = 1; j < 33; j++)
                    CN1S[r * 36 + j] = CN0S[r * 32 + j - 1];
            }
            if (t + 1 < TT) {
                y_t = Y[(b0 + r) * TT + t + 1];
                m_t = mask[(b0 + r) * TT + t + 1];
            }
        }
        __syncthreads();
    }

    // final hidden state cn0
    if (tid < 32) {
        const int r = tid;
        #pragma unroll
        for (int p = 0; p < 8; p++) {
            float4 f = *(const float4*)(CN0S + r * 32 + 4 * p);
            *(float4*)(out + O_H + (b0 + r) * 32 + 4 * p) = f;
        }
    }
}

extern "C" void kernel_launch(void* const* d_in, const int* in_sizes, int n_in,
                              void* d_out, int out_size)
{
    const float* times = (const float*)d_in[0];
    const float* Y     = (const float*)d_in[1];
    const float* mask  = (const float*)d_in[2];
    const float* A     = (const float*)d_in[3];
    const float* Bvec  = (const float*)d_in[4];
    const float* W1    = (const float*)d_in[5];
    const float* b1    = (const float*)d_in[6];
    const float* W2    = (const float*)d_in[7];
    const float* b2    = (const float*)d_in[8];
    const float* W3    = (const float*)d_in[9];
    const float* b3    = (const float*)d_in[10];
    float* out = (float*)d_out;

    cudaFuncSetAttribute(cnode_mma_kernel,
                         cudaFuncAttributeMaxDynamicSharedMemorySize, SM_TOTAL);
    cnode_mma_kernel<<<NCTA, NTH, SM_TOTAL>>>(times, Y, mask, A, Bvec,
                                              W1, b1, W2, b2, W3, b3, out);
}